// round 11
// baseline (speedup 1.0000x reference)
#include <cuda_runtime.h>
#include <cstdint>

#define NN 50000
#define NE 800000
#define AST 136  // bf16 elems per SMEM row: 128 data + 8 pad (272B stride, 16B-aligned)

// Scratch (allocation-free rule: __device__ globals)
__device__ float g_x1[NN * 128];
__device__ int g_is64;
__device__ int g_deg[NN];
__device__ int g_rowptr[NN + 1];
__device__ int g_cur[NN];
__device__ int g_esrc[NE];

// ======================= CSR build =======================
__global__ void detect_kernel(const int* __restrict__ w) {
    __shared__ int any;
    if (threadIdx.x == 0) any = 0;
    __syncthreads();
    int nz = 0;
    for (int k = threadIdx.x; k < 1024; k += blockDim.x) nz |= __ldg(w + 2 * k + 1);
    if (nz) any = 1;
    __syncthreads();
    if (threadIdx.x == 0) g_is64 = any ? 0 : 1;
}

__device__ __forceinline__ int load_dst(const void* ei_raw, int e) {
    if (g_is64) return (int)__ldg((const long long*)ei_raw + NE + e);
    return __ldg((const int*)ei_raw + NE + e);
}
__device__ __forceinline__ void load_edge(const void* ei_raw, int e, int& src, int& dst) {
    if (g_is64) {
        const long long* ei = (const long long*)ei_raw;
        src = (int)__ldg(ei + e);
        dst = (int)__ldg(ei + NE + e);
    } else {
        const int* ei = (const int*)ei_raw;
        src = __ldg(ei + e);
        dst = __ldg(ei + NE + e);
    }
}

__global__ void hist_kernel(const void* __restrict__ ei_raw) {
    int e = blockIdx.x * blockDim.x + threadIdx.x;
    if (e < NE) atomicAdd(&g_deg[load_dst(ei_raw, e)], 1);
}

__global__ void scan_kernel() {
    __shared__ int part[1024];
    const int tid = threadIdx.x;
    const int CH = (NN + 1023) / 1024;  // 49
    int base = tid * CH;
    int s = 0;
#pragma unroll 4
    for (int i = 0; i < CH; i++) {
        int idx = base + i;
        if (idx < NN) s += g_deg[idx];
    }
    part[tid] = s;
    __syncthreads();
    for (int off = 1; off < 1024; off <<= 1) {
        int t = (tid >= off) ? part[tid - off] : 0;
        __syncthreads();
        part[tid] += t;
        __syncthreads();
    }
    int run = part[tid] - s;
    for (int i = 0; i < CH; i++) {
        int idx = base + i;
        if (idx < NN) {
            g_rowptr[idx] = run;
            g_cur[idx] = run;
            run += g_deg[idx];
        }
    }
    if (tid == 0) g_rowptr[NN] = NE;
}

__global__ void fill_kernel(const void* __restrict__ ei_raw) {
    int e = blockIdx.x * blockDim.x + threadIdx.x;
    if (e < NE) {
        int src, dst;
        load_edge(ei_raw, e, src, dst);
        int p = atomicAdd(&g_cur[dst], 1);
        g_esrc[p] = src;
    }
}

// ===================== fused agg + tensor-core MLP =====================
#define TBUF (128 * AST * 2)   // 34816 B per 128x128 bf16 buffer
#define OB_W1H 0
#define OB_W1L (OB_W1H + TBUF)
#define OB_W2H (OB_W1L + TBUF)
#define OB_W2L (OB_W2H + TBUF)
#define OB_ATH (OB_W2L + TBUF)
#define OB_ATL (OB_ATH + TBUF)
#define OB_BA  (OB_ATL + TBUF)
#define OB_BB  (OB_BA + 512)
#define MLP_SMEM (OB_BB + 512)   // 209920 B

__device__ __forceinline__ uint32_t cvta_s(const void* p) {
    uint32_t r;
    asm("{ .reg .u64 t; cvta.to.shared.u64 t, %1; cvt.u32.u64 %0, t; }" : "=r"(r) : "l"(p));
    return r;
}
__device__ __forceinline__ uint32_t bfpack(float a, float b) {
    uint32_t r;
    asm("cvt.rn.bf16x2.f32 %0, %1, %2;" : "=r"(r) : "f"(b), "f"(a));
    return r;
}
__device__ __forceinline__ void split2(float a, float b, uint32_t& hi, uint32_t& lo) {
    hi = bfpack(a, b);
    float ah = __uint_as_float(hi << 16);
    float bh = __uint_as_float(hi & 0xFFFF0000u);
    lo = bfpack(a - ah, b - bh);
}
__device__ __forceinline__ void split4(float4 v, uint2& hi, uint2& lo) {
    split2(v.x, v.y, hi.x, lo.x);
    split2(v.z, v.w, hi.y, lo.y);
}

__device__ __forceinline__ void ldsm_x4(uint32_t r[4], uint32_t a) {
    asm volatile("ldmatrix.sync.aligned.m8n8.x4.shared.b16 {%0,%1,%2,%3}, [%4];"
                 : "=r"(r[0]), "=r"(r[1]), "=r"(r[2]), "=r"(r[3]) : "r"(a));
}
__device__ __forceinline__ void ldsm_x2(uint32_t r[2], uint32_t a) {
    asm volatile("ldmatrix.sync.aligned.m8n8.x2.shared.b16 {%0,%1}, [%2];"
                 : "=r"(r[0]), "=r"(r[1]) : "r"(a));
}
__device__ __forceinline__ void mma16816(float c[4], const uint32_t a[4], const uint32_t b[2]) {
    asm volatile("mma.sync.aligned.m16n8k16.row.col.f32.bf16.bf16.f32 "
                 "{%0,%1,%2,%3},{%4,%5,%6,%7},{%8,%9},{%0,%1,%2,%3};"
                 : "+f"(c[0]), "+f"(c[1]), "+f"(c[2]), "+f"(c[3])
                 : "r"(a[0]), "r"(a[1]), "r"(a[2]), "r"(a[3]), "r"(b[0]), "r"(b[1]));
}

// 16-warp variant: warp covers A rows r_base..+15, W cols c_base..+63.
__device__ __forceinline__ void mma_gemm(uint32_t sb, int offAH, int offAL, int offWH, int offWL,
                                         int lane, int r_base, int c_base, float c[8][4]) {
#pragma unroll
    for (int n = 0; n < 8; n++)
#pragma unroll
        for (int q = 0; q < 4; q++) c[n][q] = 0.f;

    const int arow = lane & 15, acol = (lane >> 4) << 3;
    const int bwrow = lane & 7, bcol = ((lane >> 3) & 1) << 3;
#pragma unroll
    for (int kt = 0; kt < 128; kt += 16) {
        uint32_t ah[4], al[4];
        {
            uint32_t bo = (uint32_t)(((r_base + arow) * AST + kt + acol) * 2);
            ldsm_x4(ah, sb + offAH + bo);
            ldsm_x4(al, sb + offAL + bo);
        }
#pragma unroll
        for (int n = 0; n < 8; n++) {
            uint32_t bo = (uint32_t)(((c_base + n * 8 + bwrow) * AST + kt + bcol) * 2);
            uint32_t bh[2], bl[2];
            ldsm_x2(bh, sb + offWH + bo);
            ldsm_x2(bl, sb + offWL + bo);
            mma16816(c[n], ah, bh);  // hi*hi
            mma16816(c[n], ah, bl);  // hi*lo
            mma16816(c[n], al, bh);  // lo*hi
        }
    }
}

template <bool RELU_OUT>
__global__ void __launch_bounds__(512, 1)
mlp_kernel(const float* __restrict__ x, const float* __restrict__ eps,
           const float* __restrict__ wA, const float* __restrict__ bA,
           const float* __restrict__ wB, const float* __restrict__ bB,
           float* __restrict__ out) {
    extern __shared__ char smem[];
    const uint32_t sb = cvta_s(smem);
    const int tid = threadIdx.x, lane = tid & 31, wid = tid >> 5;
    const int r_base = (wid & 7) * 16, c_base = (wid >> 3) * 64;
    float* ba = (float*)(smem + OB_BA);
    float* bb = (float*)(smem + OB_BB);
    const float s = 1.0f + __ldg(eps);

    // Weights -> bf16 hi/lo in SMEM (row-major [c][k], stride AST)
    for (int i = tid; i < 4096; i += 512) {
        int row = i >> 5, col = (i & 31) << 2;
        uint2 hi, lo;
        float4 v = __ldg((const float4*)wA + i);
        split4(v, hi, lo);
        *(uint2*)(smem + OB_W1H + (row * AST + col) * 2) = hi;
        *(uint2*)(smem + OB_W1L + (row * AST + col) * 2) = lo;
        v = __ldg((const float4*)wB + i);
        split4(v, hi, lo);
        *(uint2*)(smem + OB_W2H + (row * AST + col) * 2) = hi;
        *(uint2*)(smem + OB_W2L + (row * AST + col) * 2) = lo;
    }
    if (tid < 128) {
        ba[tid] = __ldg(bA + tid);
        bb[tid] = __ldg(bB + tid);
    }

    const int NT = (NN + 127) / 128;  // 391 tiles
    for (int tile = blockIdx.x; tile < NT; tile += gridDim.x) {
        int rowBase = tile << 7;
        // ---- fused A-fill: agg = (1+eps)*x[node] + sum nbrs, -> bf16 hi/lo ----
        // warp w handles rows w*8 .. w*8+7; lane owns one float4 column chunk
#pragma unroll 1
        for (int rr = 0; rr < 8; rr++) {
            int r = wid * 8 + rr;
            int node = rowBase + r;
            float4 acc = make_float4(0.f, 0.f, 0.f, 0.f);
            if (node < NN) {
                float4 a = __ldg((const float4*)(x + (size_t)node * 128) + lane);
                acc = make_float4(s * a.x, s * a.y, s * a.z, s * a.w);
                int beg = __ldg(g_rowptr + node), end = __ldg(g_rowptr + node + 1);
                int j = beg;
                for (; j + 4 <= end; j += 4) {
                    int s0 = __ldg(g_esrc + j), s1 = __ldg(g_esrc + j + 1);
                    int s2 = __ldg(g_esrc + j + 2), s3 = __ldg(g_esrc + j + 3);
                    float4 v0 = __ldg((const float4*)(x + (size_t)s0 * 128) + lane);
                    float4 v1 = __ldg((const float4*)(x + (size_t)s1 * 128) + lane);
                    float4 v2 = __ldg((const float4*)(x + (size_t)s2 * 128) + lane);
                    float4 v3 = __ldg((const float4*)(x + (size_t)s3 * 128) + lane);
                    acc.x += v0.x + v1.x; acc.y += v0.y + v1.y;
                    acc.z += v0.z + v1.z; acc.w += v0.w + v1.w;
                    acc.x += v2.x + v3.x; acc.y += v2.y + v3.y;
                    acc.z += v2.z + v3.z; acc.w += v2.w + v3.w;
                }
                for (; j < end; j++) {
                    int s0 = __ldg(g_esrc + j);
                    float4 v = __ldg((const float4*)(x + (size_t)s0 * 128) + lane);
                    acc.x += v.x; acc.y += v.y; acc.z += v.z; acc.w += v.w;
                }
            }
            uint2 hi, lo;
            split4(acc, hi, lo);
            *(uint2*)(smem + OB_ATH + (r * AST + lane * 4) * 2) = hi;
            *(uint2*)(smem + OB_ATL + (r * AST + lane * 4) * 2) = lo;
        }
        __syncthreads();

        float c[8][4];
        mma_gemm(sb, OB_ATH, OB_ATL, OB_W1H, OB_W1L, lane, r_base, c_base, c);
        __syncthreads();  // all warps done reading A before T overwrites it

        // epilogue1: bias + relu -> T (bf16 hi/lo, same buffers)
#pragma unroll
        for (int n = 0; n < 8; n++) {
            int r0 = r_base + (lane >> 2);
            int col = c_base + n * 8 + ((lane & 3) << 1);
            float b0 = ba[col], b1 = ba[col + 1];
            float v0 = fmaxf(c[n][0] + b0, 0.f);
            float v1 = fmaxf(c[n][1] + b1, 0.f);
            uint32_t h, l;
            split2(v0, v1, h, l);
            *(uint32_t*)(smem + OB_ATH + (r0 * AST + col) * 2) = h;
            *(uint32_t*)(smem + OB_ATL + (r0 * AST + col) * 2) = l;
            float v2 = fmaxf(c[n][2] + b0, 0.f);
            float v3 = fmaxf(c[n][3] + b1, 0.f);
            split2(v2, v3, h, l);
            *(uint32_t*)(smem + OB_ATH + ((r0 + 8) * AST + col) * 2) = h;
            *(uint32_t*)(smem + OB_ATL + ((r0 + 8) * AST + col) * 2) = l;
        }
        __syncthreads();

        mma_gemm(sb, OB_ATH, OB_ATL, OB_W2H, OB_W2L, lane, r_base, c_base, c);

        // epilogue2: bias [+relu] -> global
#pragma unroll
        for (int n = 0; n < 8; n++) {
            int r0 = r_base + (lane >> 2);
            int col = c_base + n * 8 + ((lane & 3) << 1);
            float b0 = bb[col], b1 = bb[col + 1];
            int gr = rowBase + r0;
            if (gr < NN) {
                float v0 = c[n][0] + b0, v1 = c[n][1] + b1;
                if (RELU_OUT) { v0 = fmaxf(v0, 0.f); v1 = fmaxf(v1, 0.f); }
                *(float2*)(out + (size_t)gr * 128 + col) = make_float2(v0, v1);
            }
            if (gr + 8 < NN) {
                float v2 = c[n][2] + b0, v3 = c[n][3] + b1;
                if (RELU_OUT) { v2 = fmaxf(v2, 0.f); v3 = fmaxf(v3, 0.f); }
                *(float2*)(out + (size_t)(gr + 8) * 128 + col) = make_float2(v2, v3);
            }
        }
        __syncthreads();  // before next tile's A fill
    }
}

extern "C" void kernel_launch(void* const* d_in, const int* in_sizes, int n_in,
                              void* d_out, int out_size) {
    const float* features = (const float*)d_in[0];
    const void*  ei       = d_in[1];
    const float* w1a      = (const float*)d_in[2];
    const float* b1a      = (const float*)d_in[3];
    const float* w1b      = (const float*)d_in[4];
    const float* b1b      = (const float*)d_in[5];
    const float* eps1     = (const float*)d_in[6];
    const float* w2a      = (const float*)d_in[7];
    const float* b2a      = (const float*)d_in[8];
    const float* w2b      = (const float*)d_in[9];
    const float* b2b      = (const float*)d_in[10];
    const float* eps2     = (const float*)d_in[11];
    float* out = (float*)d_out;

    float* x1;
    cudaGetSymbolAddress((void**)&x1, g_x1);
    int* degp;
    cudaGetSymbolAddress((void**)&degp, g_deg);

    cudaFuncSetAttribute(mlp_kernel<true>,
                         cudaFuncAttributeMaxDynamicSharedMemorySize, MLP_SMEM);
    cudaFuncSetAttribute(mlp_kernel<false>,
                         cudaFuncAttributeMaxDynamicSharedMemorySize, MLP_SMEM);

    // CSR build (once per call, reused by both layers)
    cudaMemsetAsync(degp, 0, NN * sizeof(int));
    detect_kernel<<<1, 256>>>((const int*)ei);
    hist_kernel<<<(NE + 511) / 512, 512>>>(ei);
    scan_kernel<<<1, 1024>>>();
    fill_kernel<<<(NE + 511) / 512, 512>>>(ei);

    // Layer 1: x1 = relu(MLP1(agg(features)))
    mlp_kernel<true><<<148, 512, MLP_SMEM>>>(features, eps1, w1a, b1a, w1b, b1b, x1);
    // Layer 2: out = MLP2(agg(x1))
    mlp_kernel<false><<<148, 512, MLP_SMEM>>>(x1, eps2, w2a, b2a, w2b, b2b, out);
}